// round 10
// baseline (speedup 1.0000x reference)
#include <cuda_runtime.h>
#include <cuda_fp16.h>
#include <cstdint>
#include <cstddef>

#define T_DIM 2048
#define B_DIM 8
#define H_DIM 1024
#define M_TOTAL (T_DIM * B_DIM)   // 16384
#define K_TOTAL H_DIM
#define N_TOTAL H_DIM
#define NB (B_DIM * H_DIM)        // 8192 scan chains
#define NCH 128
#define LCH 16

// ---------------- static scratch ----------------
__device__ __half g_a16[(size_t)M_TOTAL * K_TOTAL];  // x (fp16), later m (fp16)
__device__ __half g_q16[(size_t)M_TOTAL * K_TOTAL];  // q (fp16)
__device__ __half g_wq16[H_DIM * H_DIM];
__device__ __half g_wf16[H_DIM * H_DIM];
__device__ float  g_carry[NCH * NB];
__device__ float  g_inc[NCH * NB];
__device__ int    g_ctr[2];                          // dynamic tile counters

// ---------------- helpers ----------------
__device__ __forceinline__ uint32_t smem_u32(const void* p) {
    uint32_t a;
    asm("{ .reg .u64 t; cvta.to.shared.u64 t, %1; cvt.u32.u64 %0, t; }" : "=r"(a) : "l"(p));
    return a;
}
__device__ __forceinline__ uint32_t sw128(uint32_t x) { return x ^ ((x >> 3) & 0x70); }

__device__ __forceinline__ void cp16(uint32_t dst, const void* src) {
    unsigned long long g = (unsigned long long)__cvta_generic_to_global(src);
    asm volatile("cp.async.cg.shared.global [%0], [%1], 16;" :: "r"(dst), "l"(g));
}
__device__ __forceinline__ void ldsm4(uint32_t& r0, uint32_t& r1, uint32_t& r2, uint32_t& r3,
                                      uint32_t addr) {
    asm volatile("ldmatrix.sync.aligned.m8n8.x4.shared.b16 {%0,%1,%2,%3}, [%4];"
                 : "=r"(r0), "=r"(r1), "=r"(r2), "=r"(r3) : "r"(addr));
}
__device__ __forceinline__ void mma16816(float* c, const uint32_t* a, const uint32_t* b) {
    asm volatile(
        "mma.sync.aligned.m16n8k16.row.col.f32.f16.f16.f32 "
        "{%0,%1,%2,%3}, {%4,%5,%6,%7}, {%8,%9}, {%0,%1,%2,%3};"
        : "+f"(c[0]), "+f"(c[1]), "+f"(c[2]), "+f"(c[3])
        : "r"(a[0]), "r"(a[1]), "r"(a[2]), "r"(a[3]), "r"(b[0]), "r"(b[1]));
}

// ---------------- GEMM: C[m,n] = sum_k A[m,k]*W16[n,k] + bias[n] ----------------
#define TM 128
#define TN 128
#define KC 64
#define NCHUNK (K_TOTAL / KC)     // 16
#define NSTAGE 3
#define STG 32768                 // A 16KB + B 16KB
#define GEMM_SMEM (NSTAGE * STG)  // 98304
#define GTHREADS 128
#define NTILES ((M_TOTAL / TM) * (N_TOTAL / TN))   // 1024
#define GEMM_GRID 304             // 2 CTAs per SM, persistent

__device__ __forceinline__ void fill_stage(uint32_t s, int tid,
    const __half* __restrict__ A, const __half* __restrict__ B,
    int m_base, int n_base, int kb)
{
    #pragma unroll
    for (int i = 0; i < 8; ++i) {                 // A: 128 rows x 8 segs = 1024
        int seg = tid + i * 128;
        int row = seg >> 3, s8 = seg & 7;
        uint32_t sw = sw128((uint32_t)(row * 128 + s8 * 16));
        cp16(s + sw, A + (size_t)(m_base + row) * K_TOTAL + kb + s8 * 8);
    }
    #pragma unroll
    for (int i = 0; i < 8; ++i) {                 // B: 128 rows x 8 segs
        int seg = tid + i * 128;
        int row = seg >> 3, s8 = seg & 7;
        uint32_t sw = sw128((uint32_t)(row * 128 + s8 * 16));
        cp16(s + 16384 + sw, B + (size_t)(n_base + row) * K_TOTAL + kb + s8 * 8);
    }
    asm volatile("cp.async.commit_group;" ::: "memory");
}

// mode 0: store fp16, no relu.  mode 1: store fp32 with relu.
__global__ void __launch_bounds__(GTHREADS, 2) gemm_kernel(
    const __half* __restrict__ A, const __half* __restrict__ B,
    const float* __restrict__ bias, void* __restrict__ Cv, int mode)
{
    extern __shared__ char smem[];
    __shared__ int s_tile;
    uint32_t sb = smem_u32(smem);
    int tid = threadIdx.x, lane = tid & 31, wid = tid >> 5;
    int wm = wid >> 1, wn = wid & 1;              // 2 x 2 warp grid, 64x64 warp tile

    int a_row = wm * 64 + (lane & 15);
    int a_kh  = (lane >> 4) * 16;
    int bsel  = lane >> 3;
    int b_joff = (bsel >> 1) * 8;
    int b_kh   = (bsel & 1) * 16;
    int b_row0 = wn * 64 + b_joff + (lane & 7);

    while (true) {
        __syncthreads();   // prev tile smem reads done; s_tile reusable
        if (tid == 0) s_tile = atomicAdd(&g_ctr[mode], 1);
        __syncthreads();
        int tile = s_tile;
        if (tile >= NTILES) break;

        int n_base = (tile & 7) * TN;
        int m_base = (tile >> 3) * TM;

        float acc[4][8][4];
        #pragma unroll
        for (int t = 0; t < 4; ++t)
            #pragma unroll
            for (int j = 0; j < 8; ++j)
                #pragma unroll
                for (int e = 0; e < 4; ++e) acc[t][j][e] = 0.f;

        fill_stage(sb + 0 * STG, tid, A, B, m_base, n_base, 0);
        fill_stage(sb + 1 * STG, tid, A, B, m_base, n_base, KC);

        uint32_t afr[2][4][4], bfr[2][8][2];

        for (int c = 0; c < NCHUNK; ++c) {
            if (c < NCHUNK - 1) asm volatile("cp.async.wait_group 1;" ::: "memory");
            else                asm volatile("cp.async.wait_group 0;" ::: "memory");
            __syncthreads();
            if (c + 2 < NCHUNK)
                fill_stage(sb + ((c + 2) % NSTAGE) * STG, tid, A, B,
                           m_base, n_base, (c + 2) * KC);

            uint32_t sA = sb + (c % NSTAGE) * STG;
            uint32_t sB = sA + 16384;

            #pragma unroll
            for (int t = 0; t < 4; ++t)
                ldsm4(afr[0][t][0], afr[0][t][1], afr[0][t][2], afr[0][t][3],
                      sA + sw128((uint32_t)((a_row + t * 16) * 128 + a_kh)));
            #pragma unroll
            for (int jp = 0; jp < 4; ++jp) {
                uint32_t r0, r1, r2, r3;
                ldsm4(r0, r1, r2, r3,
                      sB + sw128((uint32_t)((b_row0 + jp * 16) * 128 + b_kh)));
                bfr[0][jp * 2 + 0][0] = r0; bfr[0][jp * 2 + 0][1] = r1;
                bfr[0][jp * 2 + 1][0] = r2; bfr[0][jp * 2 + 1][1] = r3;
            }

            #pragma unroll
            for (int k16 = 0; k16 < 4; ++k16) {
                int cur = k16 & 1, nxt = cur ^ 1;
                if (k16 < 3) {
                    int ko = (k16 + 1) * 32;
                    #pragma unroll
                    for (int t = 0; t < 4; ++t)
                        ldsm4(afr[nxt][t][0], afr[nxt][t][1], afr[nxt][t][2], afr[nxt][t][3],
                              sA + sw128((uint32_t)((a_row + t * 16) * 128 + ko + a_kh)));
                    #pragma unroll
                    for (int jp = 0; jp < 4; ++jp) {
                        uint32_t r0, r1, r2, r3;
                        ldsm4(r0, r1, r2, r3,
                              sB + sw128((uint32_t)((b_row0 + jp * 16) * 128 + ko + b_kh)));
                        bfr[nxt][jp * 2 + 0][0] = r0; bfr[nxt][jp * 2 + 0][1] = r1;
                        bfr[nxt][jp * 2 + 1][0] = r2; bfr[nxt][jp * 2 + 1][1] = r3;
                    }
                }
                #pragma unroll
                for (int t = 0; t < 4; ++t)
                    #pragma unroll
                    for (int j = 0; j < 8; ++j)
                        mma16816(acc[t][j], afr[cur][t], bfr[cur][j]);
            }
        }

        // epilogue
        #pragma unroll
        for (int t = 0; t < 4; ++t) {
            int r0 = m_base + wm * 64 + t * 16 + (lane >> 2);
            #pragma unroll
            for (int j = 0; j < 8; ++j) {
                int col = n_base + wn * 64 + j * 8 + (lane & 3) * 2;
                float b0 = bias[col], b1 = bias[col + 1];
                float v0 = acc[t][j][0] + b0;
                float v1 = acc[t][j][1] + b1;
                float v2 = acc[t][j][2] + b0;
                float v3 = acc[t][j][3] + b1;
                if (mode == 0) {
                    __half* Ch = (__half*)Cv;
                    *(__half2*)(Ch + (size_t)r0 * N_TOTAL + col) = __floats2half2_rn(v0, v1);
                    *(__half2*)(Ch + (size_t)(r0 + 8) * N_TOTAL + col) = __floats2half2_rn(v2, v3);
                } else {
                    float* Cf = (float*)Cv;
                    v0 = fmaxf(v0, 0.f); v1 = fmaxf(v1, 0.f);
                    v2 = fmaxf(v2, 0.f); v3 = fmaxf(v3, 0.f);
                    *(float2*)(Cf + (size_t)r0 * N_TOTAL + col) = make_float2(v0, v1);
                    *(float2*)(Cf + (size_t)(r0 + 8) * N_TOTAL + col) = make_float2(v2, v3);
                }
            }
        }
    }
}

// ---------------- fused converts + counter reset ----------------
__global__ void conv_fused(const float* __restrict__ x,
                           const float* __restrict__ wq, const float* __restrict__ wf,
                           int n4x, int n4w) {
    int i = blockIdx.x * blockDim.x + threadIdx.x;
    if (i == 0) { g_ctr[0] = 0; g_ctr[1] = 0; }
    if (i < n4x) {
        float4 v = ((const float4*)x)[i];
        __half2 h0 = __floats2half2_rn(v.x, v.y);
        __half2 h1 = __floats2half2_rn(v.z, v.w);
        uint2 o; o.x = *(uint32_t*)&h0; o.y = *(uint32_t*)&h1;
        ((uint2*)g_a16)[i] = o;
    }
    if (i < n4w) {
        float4 a = ((const float4*)wq)[i];
        float4 b = ((const float4*)wf)[i];
        __half2 qa = __floats2half2_rn(a.x, a.y), qb = __floats2half2_rn(a.z, a.w);
        __half2 fa = __floats2half2_rn(b.x, b.y), fb = __floats2half2_rn(b.z, b.w);
        uint2 oq; oq.x = *(uint32_t*)&qa; oq.y = *(uint32_t*)&qb;
        uint2 of; of.x = *(uint32_t*)&fa; of.y = *(uint32_t*)&fb;
        ((uint2*)g_wq16)[i] = oq;
        ((uint2*)g_wf16)[i] = of;
    }
}

// ---------------- scan: m_t = beta*m_{t-1} + q_t (4 chains per thread) ----------------
__device__ __forceinline__ float sigmoid_f(float x) { return 1.f / (1.f + expf(-x)); }

__global__ void scan_pass1(const float* __restrict__ beta_raw) {
    int p = blockIdx.x * blockDim.x + threadIdx.x;   // quad index, 0..NB/4-1
    int c = blockIdx.y;
    int n0 = 4 * p;
    float be0 = sigmoid_f(beta_raw[n0 & (H_DIM - 1)]);
    float be1 = sigmoid_f(beta_raw[(n0 + 1) & (H_DIM - 1)]);
    float be2 = sigmoid_f(beta_raw[(n0 + 2) & (H_DIM - 1)]);
    float be3 = sigmoid_f(beta_raw[(n0 + 3) & (H_DIM - 1)]);
    const uint2* q = (const uint2*)(g_q16 + (size_t)c * LCH * NB) + p;
    float m0 = 0.f, m1 = 0.f, m2 = 0.f, m3 = 0.f;
    #pragma unroll
    for (int i = 0; i < LCH; ++i) {
        uint2 u = q[(size_t)i * (NB / 4)];
        float2 v0 = __half22float2(*(__half2*)&u.x);
        float2 v1 = __half22float2(*(__half2*)&u.y);
        m0 = fmaf(be0, m0, v0.x);
        m1 = fmaf(be1, m1, v0.y);
        m2 = fmaf(be2, m2, v1.x);
        m3 = fmaf(be3, m3, v1.y);
    }
    *(float4*)(g_carry + c * NB + n0) = make_float4(m0, m1, m2, m3);
}
__global__ void scan_pass2(const float* __restrict__ beta_raw) {
    int n = blockIdx.x * blockDim.x + threadIdx.x;
    float beta = sigmoid_f(beta_raw[n & (H_DIM - 1)]);
    float b2 = beta * beta, b4 = b2 * b2, b8 = b4 * b4;
    float bl = b8 * b8;  // beta^16 = beta^LCH
    float P = 0.f;
    for (int c = 0; c < NCH; ++c) {
        g_inc[c * NB + n] = P;
        P = fmaf(bl, P, g_carry[c * NB + n]);
    }
}
__global__ void scan_pass3(const float* __restrict__ beta_raw) {
    int p = blockIdx.x * blockDim.x + threadIdx.x;
    int c = blockIdx.y;
    int n0 = 4 * p;
    float be0 = sigmoid_f(beta_raw[n0 & (H_DIM - 1)]);
    float be1 = sigmoid_f(beta_raw[(n0 + 1) & (H_DIM - 1)]);
    float be2 = sigmoid_f(beta_raw[(n0 + 2) & (H_DIM - 1)]);
    float be3 = sigmoid_f(beta_raw[(n0 + 3) & (H_DIM - 1)]);
    float4 mi = *(float4*)(g_inc + c * NB + n0);
    float m0 = mi.x, m1 = mi.y, m2 = mi.z, m3 = mi.w;
    const uint2* q = (const uint2*)(g_q16 + (size_t)c * LCH * NB) + p;
    uint2* a = (uint2*)(g_a16 + (size_t)c * LCH * NB) + p;
    #pragma unroll
    for (int i = 0; i < LCH; ++i) {
        uint2 u = q[(size_t)i * (NB / 4)];
        float2 v0 = __half22float2(*(__half2*)&u.x);
        float2 v1 = __half22float2(*(__half2*)&u.y);
        m0 = fmaf(be0, m0, v0.x);
        m1 = fmaf(be1, m1, v0.y);
        m2 = fmaf(be2, m2, v1.x);
        m3 = fmaf(be3, m3, v1.y);
        __half2 h0 = __floats2half2_rn(m0, m1);
        __half2 h1 = __floats2half2_rn(m2, m3);
        uint2 o; o.x = *(uint32_t*)&h0; o.y = *(uint32_t*)&h1;
        a[(size_t)i * (NB / 4)] = o;
    }
}

// ---------------- launch ----------------
extern "C" void kernel_launch(void* const* d_in, const int* in_sizes, int n_in,
                              void* d_out, int out_size) {
    (void)in_sizes; (void)n_in; (void)out_size;
    const float* x        = (const float*)d_in[0];
    const float* W_q      = (const float*)d_in[1];
    const float* b_q      = (const float*)d_in[2];
    const float* beta_raw = (const float*)d_in[3];
    const float* W_fc     = (const float*)d_in[4];
    const float* b_fc     = (const float*)d_in[5];
    float* out = (float*)d_out;

    cudaFuncSetAttribute(gemm_kernel, cudaFuncAttributeMaxDynamicSharedMemorySize, GEMM_SMEM);

    __half *wq16, *wf16, *a16, *q16;
    cudaGetSymbolAddress((void**)&wq16, g_wq16);
    cudaGetSymbolAddress((void**)&wf16, g_wf16);
    cudaGetSymbolAddress((void**)&a16,  g_a16);
    cudaGetSymbolAddress((void**)&q16,  g_q16);

    int n4x = M_TOTAL * K_TOTAL / 4;
    int n4w = H_DIM * H_DIM / 4;
    conv_fused<<<(n4x + 255) / 256, 256>>>(x, W_q, W_fc, n4x, n4w);

    gemm_kernel<<<GEMM_GRID, GTHREADS, GEMM_SMEM>>>(a16, wq16, b_q, q16, 0);

    dim3 sgrid(NB / 4 / 256, NCH);
    scan_pass1<<<sgrid, 256>>>(beta_raw);
    scan_pass2<<<NB / 256, 256>>>(beta_raw);
    scan_pass3<<<sgrid, 256>>>(beta_raw);

    gemm_kernel<<<GEMM_GRID, GTHREADS, GEMM_SMEM>>>(a16, wf16, b_fc, out, 1);
}

// round 11
// speedup vs baseline: 1.0822x; 1.0822x over previous
#include <cuda_runtime.h>
#include <cuda_fp16.h>
#include <cstdint>
#include <cstddef>

#define T_DIM 2048
#define B_DIM 8
#define H_DIM 1024
#define M_TOTAL (T_DIM * B_DIM)   // 16384
#define K_TOTAL H_DIM
#define N_TOTAL H_DIM
#define NB (B_DIM * H_DIM)        // 8192 scan chains
#define NCH 64
#define LCH 32

// ---------------- static scratch ----------------
__device__ __half g_a16[(size_t)M_TOTAL * K_TOTAL];  // x (fp16), later m (fp16)
__device__ __half g_q16[(size_t)M_TOTAL * K_TOTAL];  // q (fp16)
__device__ __half g_wq16[H_DIM * H_DIM];
__device__ __half g_wf16[H_DIM * H_DIM];
__device__ float  g_carry[NCH * NB];
__device__ float  g_inc[NCH * NB];
__device__ int    g_ctr[2];                          // dynamic tile counters

// ---------------- helpers ----------------
__device__ __forceinline__ uint32_t smem_u32(const void* p) {
    uint32_t a;
    asm("{ .reg .u64 t; cvta.to.shared.u64 t, %1; cvt.u32.u64 %0, t; }" : "=r"(a) : "l"(p));
    return a;
}
__device__ __forceinline__ uint32_t sw128(uint32_t x) { return x ^ ((x >> 3) & 0x70); }

__device__ __forceinline__ void cp16(uint32_t dst, const void* src) {
    unsigned long long g = (unsigned long long)__cvta_generic_to_global(src);
    asm volatile("cp.async.cg.shared.global [%0], [%1], 16;" :: "r"(dst), "l"(g));
}
__device__ __forceinline__ void ldsm4(uint32_t& r0, uint32_t& r1, uint32_t& r2, uint32_t& r3,
                                      uint32_t addr) {
    asm volatile("ldmatrix.sync.aligned.m8n8.x4.shared.b16 {%0,%1,%2,%3}, [%4];"
                 : "=r"(r0), "=r"(r1), "=r"(r2), "=r"(r3) : "r"(addr));
}
__device__ __forceinline__ void mma16816(float* c, const uint32_t* a, const uint32_t* b) {
    asm volatile(
        "mma.sync.aligned.m16n8k16.row.col.f32.f16.f16.f32 "
        "{%0,%1,%2,%3}, {%4,%5,%6,%7}, {%8,%9}, {%0,%1,%2,%3};"
        : "+f"(c[0]), "+f"(c[1]), "+f"(c[2]), "+f"(c[3])
        : "r"(a[0]), "r"(a[1]), "r"(a[2]), "r"(a[3]), "r"(b[0]), "r"(b[1]));
}

// ---------------- GEMM: C[m,n] = sum_k A[m,k]*W16[n,k] + bias[n] ----------------
#define TM 128
#define TN 128
#define KC 64
#define NCHUNK (K_TOTAL / KC)     // 16
#define NSTAGE 3
#define STG 32768                 // A 16KB + B 16KB
#define GEMM_SMEM (NSTAGE * STG)  // 98304
#define GTHREADS 128
#define NTILES ((M_TOTAL / TM) * (N_TOTAL / TN))   // 1024
#define GEMM_GRID 304             // 2 CTAs per SM, persistent

__device__ __forceinline__ void fill_stage(uint32_t s, int tid,
    const __half* __restrict__ A, const __half* __restrict__ B,
    int m_base, int n_base, int kb)
{
    #pragma unroll
    for (int i = 0; i < 8; ++i) {                 // A: 128 rows x 8 segs = 1024
        int seg = tid + i * 128;
        int row = seg >> 3, s8 = seg & 7;
        uint32_t sw = sw128((uint32_t)(row * 128 + s8 * 16));
        cp16(s + sw, A + (size_t)(m_base + row) * K_TOTAL + kb + s8 * 8);
    }
    #pragma unroll
    for (int i = 0; i < 8; ++i) {                 // B: 128 rows x 8 segs
        int seg = tid + i * 128;
        int row = seg >> 3, s8 = seg & 7;
        uint32_t sw = sw128((uint32_t)(row * 128 + s8 * 16));
        cp16(s + 16384 + sw, B + (size_t)(n_base + row) * K_TOTAL + kb + s8 * 8);
    }
    asm volatile("cp.async.commit_group;" ::: "memory");
}

// mode 0: store fp16, no relu.  mode 1: store fp32 with relu.
__global__ void __launch_bounds__(GTHREADS, 2) gemm_kernel(
    const __half* __restrict__ A, const __half* __restrict__ B,
    const float* __restrict__ bias, void* __restrict__ Cv, int mode)
{
    extern __shared__ char smem[];
    __shared__ int s_tile;
    uint32_t sb = smem_u32(smem);
    int tid = threadIdx.x, lane = tid & 31, wid = tid >> 5;
    int wm = wid >> 1, wn = wid & 1;              // 2 x 2 warp grid, 64x64 warp tile

    int a_row = wm * 64 + (lane & 15);
    int a_kh  = (lane >> 4) * 16;
    int bsel  = lane >> 3;
    int b_joff = (bsel >> 1) * 8;
    int b_kh   = (bsel & 1) * 16;
    int b_row0 = wn * 64 + b_joff + (lane & 7);

    while (true) {
        __syncthreads();   // prev tile smem reads done; s_tile reusable
        if (tid == 0) s_tile = atomicAdd(&g_ctr[mode], 1);
        __syncthreads();
        int tile = s_tile;
        if (tile >= NTILES) break;

        int n_base = (tile & 7) * TN;
        int m_base = (tile >> 3) * TM;

        float acc[4][8][4];
        #pragma unroll
        for (int t = 0; t < 4; ++t)
            #pragma unroll
            for (int j = 0; j < 8; ++j)
                #pragma unroll
                for (int e = 0; e < 4; ++e) acc[t][j][e] = 0.f;

        fill_stage(sb + 0 * STG, tid, A, B, m_base, n_base, 0);
        fill_stage(sb + 1 * STG, tid, A, B, m_base, n_base, KC);

        uint32_t afr[2][4][4], bfr[2][8][2];

        for (int c = 0; c < NCHUNK; ++c) {
            if (c < NCHUNK - 1) asm volatile("cp.async.wait_group 1;" ::: "memory");
            else                asm volatile("cp.async.wait_group 0;" ::: "memory");
            __syncthreads();
            if (c + 2 < NCHUNK)
                fill_stage(sb + ((c + 2) % NSTAGE) * STG, tid, A, B,
                           m_base, n_base, (c + 2) * KC);

            uint32_t sA = sb + (c % NSTAGE) * STG;
            uint32_t sB = sA + 16384;

            #pragma unroll
            for (int t = 0; t < 4; ++t)
                ldsm4(afr[0][t][0], afr[0][t][1], afr[0][t][2], afr[0][t][3],
                      sA + sw128((uint32_t)((a_row + t * 16) * 128 + a_kh)));
            #pragma unroll
            for (int jp = 0; jp < 4; ++jp) {
                uint32_t r0, r1, r2, r3;
                ldsm4(r0, r1, r2, r3,
                      sB + sw128((uint32_t)((b_row0 + jp * 16) * 128 + b_kh)));
                bfr[0][jp * 2 + 0][0] = r0; bfr[0][jp * 2 + 0][1] = r1;
                bfr[0][jp * 2 + 1][0] = r2; bfr[0][jp * 2 + 1][1] = r3;
            }

            #pragma unroll
            for (int k16 = 0; k16 < 4; ++k16) {
                int cur = k16 & 1, nxt = cur ^ 1;
                if (k16 < 3) {
                    int ko = (k16 + 1) * 32;
                    #pragma unroll
                    for (int t = 0; t < 4; ++t)
                        ldsm4(afr[nxt][t][0], afr[nxt][t][1], afr[nxt][t][2], afr[nxt][t][3],
                              sA + sw128((uint32_t)((a_row + t * 16) * 128 + ko + a_kh)));
                    #pragma unroll
                    for (int jp = 0; jp < 4; ++jp) {
                        uint32_t r0, r1, r2, r3;
                        ldsm4(r0, r1, r2, r3,
                              sB + sw128((uint32_t)((b_row0 + jp * 16) * 128 + ko + b_kh)));
                        bfr[nxt][jp * 2 + 0][0] = r0; bfr[nxt][jp * 2 + 0][1] = r1;
                        bfr[nxt][jp * 2 + 1][0] = r2; bfr[nxt][jp * 2 + 1][1] = r3;
                    }
                }
                #pragma unroll
                for (int t = 0; t < 4; ++t)
                    #pragma unroll
                    for (int j = 0; j < 8; ++j)
                        mma16816(acc[t][j], afr[cur][t], bfr[cur][j]);
            }
        }

        // epilogue
        #pragma unroll
        for (int t = 0; t < 4; ++t) {
            int r0 = m_base + wm * 64 + t * 16 + (lane >> 2);
            #pragma unroll
            for (int j = 0; j < 8; ++j) {
                int col = n_base + wn * 64 + j * 8 + (lane & 3) * 2;
                float b0 = bias[col], b1 = bias[col + 1];
                float v0 = acc[t][j][0] + b0;
                float v1 = acc[t][j][1] + b1;
                float v2 = acc[t][j][2] + b0;
                float v3 = acc[t][j][3] + b1;
                if (mode == 0) {
                    __half* Ch = (__half*)Cv;
                    *(__half2*)(Ch + (size_t)r0 * N_TOTAL + col) = __floats2half2_rn(v0, v1);
                    *(__half2*)(Ch + (size_t)(r0 + 8) * N_TOTAL + col) = __floats2half2_rn(v2, v3);
                } else {
                    float* Cf = (float*)Cv;
                    v0 = fmaxf(v0, 0.f); v1 = fmaxf(v1, 0.f);
                    v2 = fmaxf(v2, 0.f); v3 = fmaxf(v3, 0.f);
                    *(float2*)(Cf + (size_t)r0 * N_TOTAL + col) = make_float2(v0, v1);
                    *(float2*)(Cf + (size_t)(r0 + 8) * N_TOTAL + col) = make_float2(v2, v3);
                }
            }
        }
    }
}

// ---------------- fused converts + counter reset ----------------
__global__ void conv_fused(const float* __restrict__ x,
                           const float* __restrict__ wq, const float* __restrict__ wf,
                           int n4x, int n4w) {
    int i = blockIdx.x * blockDim.x + threadIdx.x;
    if (i == 0) { g_ctr[0] = 0; g_ctr[1] = 0; }
    if (i < n4x) {
        float4 v = ((const float4*)x)[i];
        __half2 h0 = __floats2half2_rn(v.x, v.y);
        __half2 h1 = __floats2half2_rn(v.z, v.w);
        uint2 o; o.x = *(uint32_t*)&h0; o.y = *(uint32_t*)&h1;
        ((uint2*)g_a16)[i] = o;
    }
    if (i < n4w) {
        float4 a = ((const float4*)wq)[i];
        float4 b = ((const float4*)wf)[i];
        __half2 qa = __floats2half2_rn(a.x, a.y), qb = __floats2half2_rn(a.z, a.w);
        __half2 fa = __floats2half2_rn(b.x, b.y), fb = __floats2half2_rn(b.z, b.w);
        uint2 oq; oq.x = *(uint32_t*)&qa; oq.y = *(uint32_t*)&qb;
        uint2 of; of.x = *(uint32_t*)&fa; of.y = *(uint32_t*)&fb;
        ((uint2*)g_wq16)[i] = oq;
        ((uint2*)g_wf16)[i] = of;
    }
}

// ---------------- scan: m_t = beta*m_{t-1} + q_t (4 chains per thread) ----------------
__device__ __forceinline__ float sigmoid_f(float x) { return 1.f / (1.f + expf(-x)); }

__global__ void scan_pass1(const float* __restrict__ beta_raw) {
    int p = blockIdx.x * blockDim.x + threadIdx.x;   // quad index, 0..NB/4-1
    int c = blockIdx.y;
    int n0 = 4 * p;
    float be0 = sigmoid_f(beta_raw[n0 & (H_DIM - 1)]);
    float be1 = sigmoid_f(beta_raw[(n0 + 1) & (H_DIM - 1)]);
    float be2 = sigmoid_f(beta_raw[(n0 + 2) & (H_DIM - 1)]);
    float be3 = sigmoid_f(beta_raw[(n0 + 3) & (H_DIM - 1)]);
    const uint2* q = (const uint2*)(g_q16 + (size_t)c * LCH * NB) + p;
    float m0 = 0.f, m1 = 0.f, m2 = 0.f, m3 = 0.f;
    #pragma unroll
    for (int i = 0; i < LCH; ++i) {
        uint2 u = q[(size_t)i * (NB / 4)];
        float2 v0 = __half22float2(*(__half2*)&u.x);
        float2 v1 = __half22float2(*(__half2*)&u.y);
        m0 = fmaf(be0, m0, v0.x);
        m1 = fmaf(be1, m1, v0.y);
        m2 = fmaf(be2, m2, v1.x);
        m3 = fmaf(be3, m3, v1.y);
    }
    *(float4*)(g_carry + c * NB + n0) = make_float4(m0, m1, m2, m3);
}

// pass 2: serial over chunks, but with batched independent loads (MLP=8)
__global__ void scan_pass2(const float* __restrict__ beta_raw) {
    int n = blockIdx.x * blockDim.x + threadIdx.x;
    float beta = sigmoid_f(beta_raw[n & (H_DIM - 1)]);
    float b2 = beta * beta, b4 = b2 * b2, b8 = b4 * b4, b16 = b8 * b8;
    float bl = b16 * b16;  // beta^32 = beta^LCH
    float P = 0.f;
    #pragma unroll
    for (int cb = 0; cb < NCH; cb += 8) {
        float v[8];
        #pragma unroll
        for (int j = 0; j < 8; ++j) v[j] = g_carry[(cb + j) * NB + n];
        #pragma unroll
        for (int j = 0; j < 8; ++j) {
            g_inc[(cb + j) * NB + n] = P;
            P = fmaf(bl, P, v[j]);
        }
    }
}

__global__ void scan_pass3(const float* __restrict__ beta_raw) {
    int p = blockIdx.x * blockDim.x + threadIdx.x;
    int c = blockIdx.y;
    int n0 = 4 * p;
    float be0 = sigmoid_f(beta_raw[n0 & (H_DIM - 1)]);
    float be1 = sigmoid_f(beta_raw[(n0 + 1) & (H_DIM - 1)]);
    float be2 = sigmoid_f(beta_raw[(n0 + 2) & (H_DIM - 1)]);
    float be3 = sigmoid_f(beta_raw[(n0 + 3) & (H_DIM - 1)]);
    float4 mi = *(float4*)(g_inc + c * NB + n0);
    float m0 = mi.x, m1 = mi.y, m2 = mi.z, m3 = mi.w;
    const uint2* q = (const uint2*)(g_q16 + (size_t)c * LCH * NB) + p;
    uint2* a = (uint2*)(g_a16 + (size_t)c * LCH * NB) + p;
    #pragma unroll
    for (int i = 0; i < LCH; ++i) {
        uint2 u = q[(size_t)i * (NB / 4)];
        float2 v0 = __half22float2(*(__half2*)&u.x);
        float2 v1 = __half22float2(*(__half2*)&u.y);
        m0 = fmaf(be0, m0, v0.x);
        m1 = fmaf(be1, m1, v0.y);
        m2 = fmaf(be2, m2, v1.x);
        m3 = fmaf(be3, m3, v1.y);
        __half2 h0 = __floats2half2_rn(m0, m1);
        __half2 h1 = __floats2half2_rn(m2, m3);
        uint2 o; o.x = *(uint32_t*)&h0; o.y = *(uint32_t*)&h1;
        a[(size_t)i * (NB / 4)] = o;
    }
}

// ---------------- launch ----------------
extern "C" void kernel_launch(void* const* d_in, const int* in_sizes, int n_in,
                              void* d_out, int out_size) {
    (void)in_sizes; (void)n_in; (void)out_size;
    const float* x        = (const float*)d_in[0];
    const float* W_q      = (const float*)d_in[1];
    const float* b_q      = (const float*)d_in[2];
    const float* beta_raw = (const float*)d_in[3];
    const float* W_fc     = (const float*)d_in[4];
    const float* b_fc     = (const float*)d_in[5];
    float* out = (float*)d_out;

    cudaFuncSetAttribute(gemm_kernel, cudaFuncAttributeMaxDynamicSharedMemorySize, GEMM_SMEM);

    __half *wq16, *wf16, *a16, *q16;
    cudaGetSymbolAddress((void**)&wq16, g_wq16);
    cudaGetSymbolAddress((void**)&wf16, g_wf16);
    cudaGetSymbolAddress((void**)&a16,  g_a16);
    cudaGetSymbolAddress((void**)&q16,  g_q16);

    int n4x = M_TOTAL * K_TOTAL / 4;
    int n4w = H_DIM * H_DIM / 4;
    conv_fused<<<(n4x + 255) / 256, 256>>>(x, W_q, W_fc, n4x, n4w);

    gemm_kernel<<<GEMM_GRID, GTHREADS, GEMM_SMEM>>>(a16, wq16, b_q, q16, 0);

    dim3 sgrid(NB / 4 / 256, NCH);
    scan_pass1<<<sgrid, 256>>>(beta_raw);
    scan_pass2<<<NB / 256, 256>>>(beta_raw);
    scan_pass3<<<sgrid, 256>>>(beta_raw);

    gemm_kernel<<<GEMM_GRID, GTHREADS, GEMM_SMEM>>>(a16, wf16, b_fc, out, 1);
}

// round 12
// speedup vs baseline: 1.2525x; 1.1573x over previous
#include <cuda_runtime.h>
#include <cuda_fp16.h>
#include <cstdint>
#include <cstddef>

#define T_DIM 2048
#define B_DIM 8
#define H_DIM 1024
#define M_TOTAL (T_DIM * B_DIM)   // 16384
#define K_TOTAL H_DIM
#define N_TOTAL H_DIM
#define NB (B_DIM * H_DIM)        // 8192 scan chains
#define NCH 64
#define LCH 32

// ---------------- static scratch ----------------
__device__ __half g_a16[(size_t)M_TOTAL * K_TOTAL];  // x (fp16), later m (fp16)
__device__ __half g_q16[(size_t)M_TOTAL * K_TOTAL];  // q (fp16)
__device__ __half g_wq16[H_DIM * H_DIM];
__device__ __half g_wf16[H_DIM * H_DIM];
__device__ float  g_carry[NCH * NB];
__device__ float  g_inc[NCH * NB];

// ---------------- helpers ----------------
__device__ __forceinline__ uint32_t smem_u32(const void* p) {
    uint32_t a;
    asm("{ .reg .u64 t; cvta.to.shared.u64 t, %1; cvt.u32.u64 %0, t; }" : "=r"(a) : "l"(p));
    return a;
}
__device__ __forceinline__ uint32_t sw128(uint32_t x) { return x ^ ((x >> 3) & 0x70); }

__device__ __forceinline__ void cp16(uint32_t dst, const void* src) {
    unsigned long long g = (unsigned long long)__cvta_generic_to_global(src);
    asm volatile("cp.async.cg.shared.global [%0], [%1], 16;" :: "r"(dst), "l"(g));
}
__device__ __forceinline__ void ldsm4(uint32_t& r0, uint32_t& r1, uint32_t& r2, uint32_t& r3,
                                      uint32_t addr) {
    asm volatile("ldmatrix.sync.aligned.m8n8.x4.shared.b16 {%0,%1,%2,%3}, [%4];"
                 : "=r"(r0), "=r"(r1), "=r"(r2), "=r"(r3) : "r"(addr));
}
__device__ __forceinline__ void mma16816(float* c, const uint32_t* a, const uint32_t* b) {
    asm volatile(
        "mma.sync.aligned.m16n8k16.row.col.f32.f16.f16.f32 "
        "{%0,%1,%2,%3}, {%4,%5,%6,%7}, {%8,%9}, {%0,%1,%2,%3};"
        : "+f"(c[0]), "+f"(c[1]), "+f"(c[2]), "+f"(c[3])
        : "r"(a[0]), "r"(a[1]), "r"(a[2]), "r"(a[3]), "r"(b[0]), "r"(b[1]));
}

// ---------------- GEMM: C[m,n] = sum_k A[m,k]*W16[n,k] + bias[n] ----------------
#define TM 128
#define TN 128
#define KC 64
#define NCHUNK (K_TOTAL / KC)     // 16
#define NSTAGE 3
#define STG 32768                 // A 16KB + B 16KB
#define GEMM_SMEM (NSTAGE * STG)  // 98304
#define GTHREADS 128
#define NTILES ((M_TOTAL / TM) * (N_TOTAL / TN))   // 1024
#define GEMM_GRID 304             // 2 CTAs per SM, persistent

__device__ __forceinline__ void fill_stage(uint32_t s, int tid,
    const __half* __restrict__ A, const __half* __restrict__ B,
    int m_base, int n_base, int kb)
{
    #pragma unroll
    for (int i = 0; i < 8; ++i) {                 // A: 128 rows x 8 segs = 1024
        int seg = tid + i * 128;
        int row = seg >> 3, s8 = seg & 7;
        uint32_t sw = sw128((uint32_t)(row * 128 + s8 * 16));
        cp16(s + sw, A + (size_t)(m_base + row) * K_TOTAL + kb + s8 * 8);
    }
    #pragma unroll
    for (int i = 0; i < 8; ++i) {                 // B: 128 rows x 8 segs
        int seg = tid + i * 128;
        int row = seg >> 3, s8 = seg & 7;
        uint32_t sw = sw128((uint32_t)(row * 128 + s8 * 16));
        cp16(s + 16384 + sw, B + (size_t)(n_base + row) * K_TOTAL + kb + s8 * 8);
    }
    asm volatile("cp.async.commit_group;" ::: "memory");
}

// mode 0: store fp16, no relu.  mode 1: store fp32 with relu.
__global__ void __launch_bounds__(GTHREADS, 2) gemm_kernel(
    const __half* __restrict__ A, const __half* __restrict__ B,
    const float* __restrict__ bias, void* __restrict__ Cv, int mode)
{
    extern __shared__ char smem[];
    uint32_t sb = smem_u32(smem);
    int tid = threadIdx.x, lane = tid & 31, wid = tid >> 5;
    int wm = wid >> 1, wn = wid & 1;              // 2 x 2 warp grid, 64x64 warp tile

    int a_row = wm * 64 + (lane & 15);
    int a_kh  = (lane >> 4) * 16;
    int bsel  = lane >> 3;
    int b_joff = (bsel >> 1) * 8;
    int b_kh   = (bsel & 1) * 16;
    int b_row0 = wn * 64 + b_joff + (lane & 7);

    for (int tile = blockIdx.x; tile < NTILES; tile += gridDim.x) {
        int n_base = (tile & 7) * TN;
        int m_base = (tile >> 3) * TM;

        __syncthreads();   // previous tile's smem reads done before refill

        float acc[4][8][4];
        #pragma unroll
        for (int t = 0; t < 4; ++t)
            #pragma unroll
            for (int j = 0; j < 8; ++j)
                #pragma unroll
                for (int e = 0; e < 4; ++e) acc[t][j][e] = 0.f;

        fill_stage(sb + 0 * STG, tid, A, B, m_base, n_base, 0);
        fill_stage(sb + 1 * STG, tid, A, B, m_base, n_base, KC);

        uint32_t afr[2][4][4], bfr[2][8][2];

        for (int c = 0; c < NCHUNK; ++c) {
            if (c < NCHUNK - 1) asm volatile("cp.async.wait_group 1;" ::: "memory");
            else                asm volatile("cp.async.wait_group 0;" ::: "memory");
            __syncthreads();
            if (c + 2 < NCHUNK)
                fill_stage(sb + ((c + 2) % NSTAGE) * STG, tid, A, B,
                           m_base, n_base, (c + 2) * KC);

            uint32_t sA = sb + (c % NSTAGE) * STG;
            uint32_t sB = sA + 16384;

            #pragma unroll
            for (int t = 0; t < 4; ++t)
                ldsm4(afr[0][t][0], afr[0][t][1], afr[0][t][2], afr[0][t][3],
                      sA + sw128((uint32_t)((a_row + t * 16) * 128 + a_kh)));
            #pragma unroll
            for (int jp = 0; jp < 4; ++jp) {
                uint32_t r0, r1, r2, r3;
                ldsm4(r0, r1, r2, r3,
                      sB + sw128((uint32_t)((b_row0 + jp * 16) * 128 + b_kh)));
                bfr[0][jp * 2 + 0][0] = r0; bfr[0][jp * 2 + 0][1] = r1;
                bfr[0][jp * 2 + 1][0] = r2; bfr[0][jp * 2 + 1][1] = r3;
            }

            #pragma unroll
            for (int k16 = 0; k16 < 4; ++k16) {
                int cur = k16 & 1, nxt = cur ^ 1;
                if (k16 < 3) {
                    int ko = (k16 + 1) * 32;
                    #pragma unroll
                    for (int t = 0; t < 4; ++t)
                        ldsm4(afr[nxt][t][0], afr[nxt][t][1], afr[nxt][t][2], afr[nxt][t][3],
                              sA + sw128((uint32_t)((a_row + t * 16) * 128 + ko + a_kh)));
                    #pragma unroll
                    for (int jp = 0; jp < 4; ++jp) {
                        uint32_t r0, r1, r2, r3;
                        ldsm4(r0, r1, r2, r3,
                              sB + sw128((uint32_t)((b_row0 + jp * 16) * 128 + ko + b_kh)));
                        bfr[nxt][jp * 2 + 0][0] = r0; bfr[nxt][jp * 2 + 0][1] = r1;
                        bfr[nxt][jp * 2 + 1][0] = r2; bfr[nxt][jp * 2 + 1][1] = r3;
                    }
                }
                #pragma unroll
                for (int t = 0; t < 4; ++t)
                    #pragma unroll
                    for (int j = 0; j < 8; ++j)
                        mma16816(acc[t][j], afr[cur][t], bfr[cur][j]);
            }
        }

        // epilogue
        #pragma unroll
        for (int t = 0; t < 4; ++t) {
            int r0 = m_base + wm * 64 + t * 16 + (lane >> 2);
            #pragma unroll
            for (int j = 0; j < 8; ++j) {
                int col = n_base + wn * 64 + j * 8 + (lane & 3) * 2;
                float b0 = bias[col], b1 = bias[col + 1];
                float v0 = acc[t][j][0] + b0;
                float v1 = acc[t][j][1] + b1;
                float v2 = acc[t][j][2] + b0;
                float v3 = acc[t][j][3] + b1;
                if (mode == 0) {
                    __half* Ch = (__half*)Cv;
                    *(__half2*)(Ch + (size_t)r0 * N_TOTAL + col) = __floats2half2_rn(v0, v1);
                    *(__half2*)(Ch + (size_t)(r0 + 8) * N_TOTAL + col) = __floats2half2_rn(v2, v3);
                } else {
                    float* Cf = (float*)Cv;
                    v0 = fmaxf(v0, 0.f); v1 = fmaxf(v1, 0.f);
                    v2 = fmaxf(v2, 0.f); v3 = fmaxf(v3, 0.f);
                    *(float2*)(Cf + (size_t)r0 * N_TOTAL + col) = make_float2(v0, v1);
                    *(float2*)(Cf + (size_t)(r0 + 8) * N_TOTAL + col) = make_float2(v2, v3);
                }
            }
        }
    }
}

// ---------------- fused converts ----------------
__global__ void conv_fused(const float* __restrict__ x,
                           const float* __restrict__ wq, const float* __restrict__ wf,
                           int n4x, int n4w) {
    int i = blockIdx.x * blockDim.x + threadIdx.x;
    if (i < n4x) {
        float4 v = ((const float4*)x)[i];
        __half2 h0 = __floats2half2_rn(v.x, v.y);
        __half2 h1 = __floats2half2_rn(v.z, v.w);
        uint2 o; o.x = *(uint32_t*)&h0; o.y = *(uint32_t*)&h1;
        ((uint2*)g_a16)[i] = o;
    }
    if (i < n4w) {
        float4 a = ((const float4*)wq)[i];
        float4 b = ((const float4*)wf)[i];
        __half2 qa = __floats2half2_rn(a.x, a.y), qb = __floats2half2_rn(a.z, a.w);
        __half2 fa = __floats2half2_rn(b.x, b.y), fb = __floats2half2_rn(b.z, b.w);
        uint2 oq; oq.x = *(uint32_t*)&qa; oq.y = *(uint32_t*)&qb;
        uint2 of; of.x = *(uint32_t*)&fa; of.y = *(uint32_t*)&fb;
        ((uint2*)g_wq16)[i] = oq;
        ((uint2*)g_wf16)[i] = of;
    }
}

// ---------------- scan: m_t = beta*m_{t-1} + q_t (4 chains per thread) ----------------
__device__ __forceinline__ float sigmoid_f(float x) { return 1.f / (1.f + expf(-x)); }

__global__ void scan_pass1(const float* __restrict__ beta_raw) {
    int p = blockIdx.x * blockDim.x + threadIdx.x;   // quad index, 0..NB/4-1
    int c = blockIdx.y;
    int n0 = 4 * p;
    float be0 = sigmoid_f(beta_raw[n0 & (H_DIM - 1)]);
    float be1 = sigmoid_f(beta_raw[(n0 + 1) & (H_DIM - 1)]);
    float be2 = sigmoid_f(beta_raw[(n0 + 2) & (H_DIM - 1)]);
    float be3 = sigmoid_f(beta_raw[(n0 + 3) & (H_DIM - 1)]);
    const uint2* q = (const uint2*)(g_q16 + (size_t)c * LCH * NB) + p;
    float m0 = 0.f, m1 = 0.f, m2 = 0.f, m3 = 0.f;
    #pragma unroll
    for (int i = 0; i < LCH; ++i) {
        uint2 u = q[(size_t)i * (NB / 4)];
        float2 v0 = __half22float2(*(__half2*)&u.x);
        float2 v1 = __half22float2(*(__half2*)&u.y);
        m0 = fmaf(be0, m0, v0.x);
        m1 = fmaf(be1, m1, v0.y);
        m2 = fmaf(be2, m2, v1.x);
        m3 = fmaf(be3, m3, v1.y);
    }
    *(float4*)(g_carry + c * NB + n0) = make_float4(m0, m1, m2, m3);
}

// pass 2: serial over chunks, batched independent loads (MLP=8)
__global__ void scan_pass2(const float* __restrict__ beta_raw) {
    int n = blockIdx.x * blockDim.x + threadIdx.x;
    float beta = sigmoid_f(beta_raw[n & (H_DIM - 1)]);
    float b2 = beta * beta, b4 = b2 * b2, b8 = b4 * b4, b16 = b8 * b8;
    float bl = b16 * b16;  // beta^32 = beta^LCH
    float P = 0.f;
    #pragma unroll
    for (int cb = 0; cb < NCH; cb += 8) {
        float v[8];
        #pragma unroll
        for (int j = 0; j < 8; ++j) v[j] = g_carry[(cb + j) * NB + n];
        #pragma unroll
        for (int j = 0; j < 8; ++j) {
            g_inc[(cb + j) * NB + n] = P;
            P = fmaf(bl, P, v[j]);
        }
    }
}

__global__ void scan_pass3(const float* __restrict__ beta_raw) {
    int p = blockIdx.x * blockDim.x + threadIdx.x;
    int c = blockIdx.y;
    int n0 = 4 * p;
    float be0 = sigmoid_f(beta_raw[n0 & (H_DIM - 1)]);
    float be1 = sigmoid_f(beta_raw[(n0 + 1) & (H_DIM - 1)]);
    float be2 = sigmoid_f(beta_raw[(n0 + 2) & (H_DIM - 1)]);
    float be3 = sigmoid_f(beta_raw[(n0 + 3) & (H_DIM - 1)]);
    float4 mi = *(float4*)(g_inc + c * NB + n0);
    float m0 = mi.x, m1 = mi.y, m2 = mi.z, m3 = mi.w;
    const uint2* q = (const uint2*)(g_q16 + (size_t)c * LCH * NB) + p;
    uint2* a = (uint2*)(g_a16 + (size_t)c * LCH * NB) + p;
    #pragma unroll
    for (int i = 0; i < LCH; ++i) {
        uint2 u = q[(size_t)i * (NB / 4)];
        float2 v0 = __half22float2(*(__half2*)&u.x);
        float2 v1 = __half22float2(*(__half2*)&u.y);
        m0 = fmaf(be0, m0, v0.x);
        m1 = fmaf(be1, m1, v0.y);
        m2 = fmaf(be2, m2, v1.x);
        m3 = fmaf(be3, m3, v1.y);
        __half2 h0 = __floats2half2_rn(m0, m1);
        __half2 h1 = __floats2half2_rn(m2, m3);
        uint2 o; o.x = *(uint32_t*)&h0; o.y = *(uint32_t*)&h1;
        a[(size_t)i * (NB / 4)] = o;
    }
}

// ---------------- launch ----------------
extern "C" void kernel_launch(void* const* d_in, const int* in_sizes, int n_in,
                              void* d_out, int out_size) {
    (void)in_sizes; (void)n_in; (void)out_size;
    const float* x        = (const float*)d_in[0];
    const float* W_q      = (const float*)d_in[1];
    const float* b_q      = (const float*)d_in[2];
    const float* beta_raw = (const float*)d_in[3];
    const float* W_fc     = (const float*)d_in[4];
    const float* b_fc     = (const float*)d_in[5];
    float* out = (float*)d_out;

    cudaFuncSetAttribute(gemm_kernel, cudaFuncAttributeMaxDynamicSharedMemorySize, GEMM_SMEM);

    __half *wq16, *wf16, *a16, *q16;
    cudaGetSymbolAddress((void**)&wq16, g_wq16);
    cudaGetSymbolAddress((void**)&wf16, g_wf16);
    cudaGetSymbolAddress((void**)&a16,  g_a16);
    cudaGetSymbolAddress((void**)&q16,  g_q16);

    int n4x = M_TOTAL * K_TOTAL / 4;
    int n4w = H_DIM * H_DIM / 4;
    conv_fused<<<(n4x + 255) / 256, 256>>>(x, W_q, W_fc, n4x, n4w);

    gemm_kernel<<<GEMM_GRID, GTHREADS, GEMM_SMEM>>>(a16, wq16, b_q, q16, 0);

    dim3 sgrid(NB / 4 / 256, NCH);
    scan_pass1<<<sgrid, 256>>>(beta_raw);
    scan_pass2<<<NB / 256, 256>>>(beta_raw);
    scan_pass3<<<sgrid, 256>>>(beta_raw);

    gemm_kernel<<<GEMM_GRID, GTHREADS, GEMM_SMEM>>>(a16, wf16, b_fc, out, 1);
}

// round 13
// speedup vs baseline: 1.2751x; 1.0181x over previous
#include <cuda_runtime.h>
#include <cuda_fp16.h>
#include <cstdint>
#include <cstddef>

#define T_DIM 2048
#define B_DIM 8
#define H_DIM 1024
#define M_TOTAL (T_DIM * B_DIM)   // 16384
#define K_TOTAL H_DIM
#define N_TOTAL H_DIM
#define NB (B_DIM * H_DIM)        // 8192 scan chains
#define NCH 64
#define LCH 32

// ---------------- static scratch ----------------
__device__ __half g_a16[(size_t)M_TOTAL * K_TOTAL];  // x (fp16), later m (fp16)
__device__ __half g_q16[(size_t)M_TOTAL * K_TOTAL];  // q (fp16)
__device__ __half g_wq16[H_DIM * H_DIM];
__device__ __half g_wf16[H_DIM * H_DIM];
__device__ float  g_carry[NCH * NB];
__device__ float  g_inc[NCH * NB];

// ---------------- helpers ----------------
__device__ __forceinline__ uint32_t smem_u32(const void* p) {
    uint32_t a;
    asm("{ .reg .u64 t; cvta.to.shared.u64 t, %1; cvt.u32.u64 %0, t; }" : "=r"(a) : "l"(p));
    return a;
}
__device__ __forceinline__ uint32_t sw128(uint32_t x) { return x ^ ((x >> 3) & 0x70); }

__device__ __forceinline__ void cp16(uint32_t dst, const void* src) {
    unsigned long long g = (unsigned long long)__cvta_generic_to_global(src);
    asm volatile("cp.async.cg.shared.global [%0], [%1], 16;" :: "r"(dst), "l"(g));
}
__device__ __forceinline__ void ldsm4(uint32_t& r0, uint32_t& r1, uint32_t& r2, uint32_t& r3,
                                      uint32_t addr) {
    asm volatile("ldmatrix.sync.aligned.m8n8.x4.shared.b16 {%0,%1,%2,%3}, [%4];"
                 : "=r"(r0), "=r"(r1), "=r"(r2), "=r"(r3) : "r"(addr));
}
__device__ __forceinline__ void mma16816(float* c, const uint32_t* a, const uint32_t* b) {
    asm volatile(
        "mma.sync.aligned.m16n8k16.row.col.f32.f16.f16.f32 "
        "{%0,%1,%2,%3}, {%4,%5,%6,%7}, {%8,%9}, {%0,%1,%2,%3};"
        : "+f"(c[0]), "+f"(c[1]), "+f"(c[2]), "+f"(c[3])
        : "r"(a[0]), "r"(a[1]), "r"(a[2]), "r"(a[3]), "r"(b[0]), "r"(b[1]));
}

// ---------------- GEMM: C[m,n] = sum_k A[m,k]*W16[n,k] + bias[n] ----------------
#define TM 128
#define TN 128
#define KC 64
#define NCHUNK (K_TOTAL / KC)     // 16
#define NSTAGE 3
#define STG 32768                 // A 16KB + B 16KB
#define GEMM_SMEM (NSTAGE * STG)  // 98304
#define GTHREADS 128
#define NTILES ((M_TOTAL / TM) * (N_TOTAL / TN))   // 1024
#define GEMM_GRID 304             // 2 CTAs per SM, persistent

__device__ __forceinline__ void fill_stage(uint32_t s, int tid,
    const __half* __restrict__ A, const __half* __restrict__ B,
    int m_base, int n_base, int kb)
{
    #pragma unroll
    for (int i = 0; i < 8; ++i) {                 // A: 128 rows x 8 segs = 1024
        int seg = tid + i * 128;
        int row = seg >> 3, s8 = seg & 7;
        uint32_t sw = sw128((uint32_t)(row * 128 + s8 * 16));
        cp16(s + sw, A + (size_t)(m_base + row) * K_TOTAL + kb + s8 * 8);
    }
    #pragma unroll
    for (int i = 0; i < 8; ++i) {                 // B: 128 rows x 8 segs
        int seg = tid + i * 128;
        int row = seg >> 3, s8 = seg & 7;
        uint32_t sw = sw128((uint32_t)(row * 128 + s8 * 16));
        cp16(s + 16384 + sw, B + (size_t)(n_base + row) * K_TOTAL + kb + s8 * 8);
    }
    asm volatile("cp.async.commit_group;" ::: "memory");
}

// mode 0: store fp16, no relu.  mode 1: store fp32 with relu.
// Flat (tile, chunk) pipeline: stage cursor rolls continuously across tiles,
// so next tile's fills overlap previous tile's last chunks + epilogue.
__global__ void __launch_bounds__(GTHREADS, 2) gemm_kernel(
    const __half* __restrict__ A, const __half* __restrict__ B,
    const float* __restrict__ bias, void* __restrict__ Cv, int mode)
{
    extern __shared__ char smem[];
    uint32_t sb = smem_u32(smem);
    int tid = threadIdx.x, lane = tid & 31, wid = tid >> 5;
    int wm = wid >> 1, wn = wid & 1;              // 2 x 2 warp grid, 64x64 warp tile

    int a_row = wm * 64 + (lane & 15);
    int a_kh  = (lane >> 4) * 16;
    int bsel  = lane >> 3;
    int b_joff = (bsel >> 1) * 8;
    int b_kh   = (bsel & 1) * 16;
    int b_row0 = wn * 64 + b_joff + (lane & 7);

    int ntile_cta = (NTILES - blockIdx.x + GEMM_GRID - 1) / GEMM_GRID;
    if (ntile_cta <= 0) return;
    int total = ntile_cta * NCHUNK;               // global chunk count for this CTA

    float acc[4][8][4];
    #pragma unroll
    for (int t = 0; t < 4; ++t)
        #pragma unroll
        for (int j = 0; j < 8; ++j)
            #pragma unroll
            for (int e = 0; e < 4; ++e) acc[t][j][e] = 0.f;

    // prologue: fill gc = 0, 1 (both belong to first tile since NCHUNK >= 2)
    {
        int t0 = blockIdx.x;
        int nb = (t0 & 7) * TN, mb = (t0 >> 3) * TM;
        fill_stage(sb + 0 * STG, tid, A, B, mb, nb, 0);
        if (total > 1) fill_stage(sb + 1 * STG, tid, A, B, mb, nb, KC);
    }

    uint32_t afr[2][4][4], bfr[2][8][2];

    for (int gc = 0; gc < total; ++gc) {
        if (gc < total - 1) asm volatile("cp.async.wait_group 1;" ::: "memory");
        else                asm volatile("cp.async.wait_group 0;" ::: "memory");
        __syncthreads();

        int gf = gc + 2;
        if (gf < total) {
            int tf = blockIdx.x + (gf >> 4) * GEMM_GRID;
            int nb = (tf & 7) * TN, mb = (tf >> 3) * TM;
            fill_stage(sb + (gf % NSTAGE) * STG, tid, A, B, mb, nb, (gf & 15) * KC);
        } else {
            asm volatile("cp.async.commit_group;" ::: "memory");  // keep group accounting
        }

        uint32_t sA = sb + (gc % NSTAGE) * STG;
        uint32_t sB = sA + 16384;

        #pragma unroll
        for (int t = 0; t < 4; ++t)
            ldsm4(afr[0][t][0], afr[0][t][1], afr[0][t][2], afr[0][t][3],
                  sA + sw128((uint32_t)((a_row + t * 16) * 128 + a_kh)));
        #pragma unroll
        for (int jp = 0; jp < 4; ++jp) {
            uint32_t r0, r1, r2, r3;
            ldsm4(r0, r1, r2, r3,
                  sB + sw128((uint32_t)((b_row0 + jp * 16) * 128 + b_kh)));
            bfr[0][jp * 2 + 0][0] = r0; bfr[0][jp * 2 + 0][1] = r1;
            bfr[0][jp * 2 + 1][0] = r2; bfr[0][jp * 2 + 1][1] = r3;
        }

        #pragma unroll
        for (int k16 = 0; k16 < 4; ++k16) {
            int cur = k16 & 1, nxt = cur ^ 1;
            if (k16 < 3) {
                int ko = (k16 + 1) * 32;
                #pragma unroll
                for (int t = 0; t < 4; ++t)
                    ldsm4(afr[nxt][t][0], afr[nxt][t][1], afr[nxt][t][2], afr[nxt][t][3],
                          sA + sw128((uint32_t)((a_row + t * 16) * 128 + ko + a_kh)));
                #pragma unroll
                for (int jp = 0; jp < 4; ++jp) {
                    uint32_t r0, r1, r2, r3;
                    ldsm4(r0, r1, r2, r3,
                          sB + sw128((uint32_t)((b_row0 + jp * 16) * 128 + ko + b_kh)));
                    bfr[nxt][jp * 2 + 0][0] = r0; bfr[nxt][jp * 2 + 0][1] = r1;
                    bfr[nxt][jp * 2 + 1][0] = r2; bfr[nxt][jp * 2 + 1][1] = r3;
                }
            }
            #pragma unroll
            for (int t = 0; t < 4; ++t)
                #pragma unroll
                for (int j = 0; j < 8; ++j)
                    mma16816(acc[t][j], afr[cur][t], bfr[cur][j]);
        }

        if ((gc & 15) == 15) {
            // epilogue for the tile just finished; fills for next tile already in flight
            int tc = blockIdx.x + (gc >> 4) * GEMM_GRID;
            int n_base = (tc & 7) * TN, m_base = (tc >> 3) * TM;
            #pragma unroll
            for (int t = 0; t < 4; ++t) {
                int r0 = m_base + wm * 64 + t * 16 + (lane >> 2);
                #pragma unroll
                for (int j = 0; j < 8; ++j) {
                    int col = n_base + wn * 64 + j * 8 + (lane & 3) * 2;
                    float b0 = bias[col], b1 = bias[col + 1];
                    float v0 = acc[t][j][0] + b0;
                    float v1 = acc[t][j][1] + b1;
                    float v2 = acc[t][j][2] + b0;
                    float v3 = acc[t][j][3] + b1;
                    if (mode == 0) {
                        __half* Ch = (__half*)Cv;
                        *(__half2*)(Ch + (size_t)r0 * N_TOTAL + col) = __floats2half2_rn(v0, v1);
                        *(__half2*)(Ch + (size_t)(r0 + 8) * N_TOTAL + col) = __floats2half2_rn(v2, v3);
                    } else {
                        float* Cf = (float*)Cv;
                        v0 = fmaxf(v0, 0.f); v1 = fmaxf(v1, 0.f);
                        v2 = fmaxf(v2, 0.f); v3 = fmaxf(v3, 0.f);
                        *(float2*)(Cf + (size_t)r0 * N_TOTAL + col) = make_float2(v0, v1);
                        *(float2*)(Cf + (size_t)(r0 + 8) * N_TOTAL + col) = make_float2(v2, v3);
                    }
                    acc[t][j][0] = 0.f; acc[t][j][1] = 0.f;
                    acc[t][j][2] = 0.f; acc[t][j][3] = 0.f;
                }
            }
        }
    }
}

// ---------------- fused converts ----------------
__global__ void conv_fused(const float* __restrict__ x,
                           const float* __restrict__ wq, const float* __restrict__ wf,
                           int n4x, int n4w) {
    int i = blockIdx.x * blockDim.x + threadIdx.x;
    if (i < n4x) {
        float4 v = ((const float4*)x)[i];
        __half2 h0 = __floats2half2_rn(v.x, v.y);
        __half2 h1 = __floats2half2_rn(v.z, v.w);
        uint2 o; o.x = *(uint32_t*)&h0; o.y = *(uint32_t*)&h1;
        ((uint2*)g_a16)[i] = o;
    }
    if (i < n4w) {
        float4 a = ((const float4*)wq)[i];
        float4 b = ((const float4*)wf)[i];
        __half2 qa = __floats2half2_rn(a.x, a.y), qb = __floats2half2_rn(a.z, a.w);
        __half2 fa = __floats2half2_rn(b.x, b.y), fb = __floats2half2_rn(b.z, b.w);
        uint2 oq; oq.x = *(uint32_t*)&qa; oq.y = *(uint32_t*)&qb;
        uint2 of; of.x = *(uint32_t*)&fa; of.y = *(uint32_t*)&fb;
        ((uint2*)g_wq16)[i] = oq;
        ((uint2*)g_wf16)[i] = of;
    }
}

// ---------------- scan: m_t = beta*m_{t-1} + q_t (4 chains per thread) ----------------
__device__ __forceinline__ float sigmoid_f(float x) { return 1.f / (1.f + expf(-x)); }

__global__ void scan_pass1(const float* __restrict__ beta_raw) {
    int p = blockIdx.x * blockDim.x + threadIdx.x;   // quad index, 0..NB/4-1
    int c = blockIdx.y;
    int n0 = 4 * p;
    float be0 = sigmoid_f(beta_raw[n0 & (H_DIM - 1)]);
    float be1 = sigmoid_f(beta_raw[(n0 + 1) & (H_DIM - 1)]);
    float be2 = sigmoid_f(beta_raw[(n0 + 2) & (H_DIM - 1)]);
    float be3 = sigmoid_f(beta_raw[(n0 + 3) & (H_DIM - 1)]);
    const uint2* q = (const uint2*)(g_q16 + (size_t)c * LCH * NB) + p;
    float m0 = 0.f, m1 = 0.f, m2 = 0.f, m3 = 0.f;
    #pragma unroll
    for (int i = 0; i < LCH; ++i) {
        uint2 u = q[(size_t)i * (NB / 4)];
        float2 v0 = __half22float2(*(__half2*)&u.x);
        float2 v1 = __half22float2(*(__half2*)&u.y);
        m0 = fmaf(be0, m0, v0.x);
        m1 = fmaf(be1, m1, v0.y);
        m2 = fmaf(be2, m2, v1.x);
        m3 = fmaf(be3, m3, v1.y);
    }
    *(float4*)(g_carry + c * NB + n0) = make_float4(m0, m1, m2, m3);
}

// pass 2: serial over chunks, batched independent loads (MLP=8)
__global__ void scan_pass2(const float* __restrict__ beta_raw) {
    int n = blockIdx.x * blockDim.x + threadIdx.x;
    float beta = sigmoid_f(beta_raw[n & (H_DIM - 1)]);
    float b2 = beta * beta, b4 = b2 * b2, b8 = b4 * b4, b16 = b8 * b8;
    float bl = b16 * b16;  // beta^32 = beta^LCH
    float P = 0.f;
    #pragma unroll
    for (int cb = 0; cb < NCH; cb += 8) {
        float v[8];
        #pragma unroll
        for (int j = 0; j < 8; ++j) v[j] = g_carry[(cb + j) * NB + n];
        #pragma unroll
        for (int j = 0; j < 8; ++j) {
            g_inc[(cb + j) * NB + n] = P;
            P = fmaf(bl, P, v[j]);
        }
    }
}

__global__ void scan_pass3(const float* __restrict__ beta_raw) {
    int p = blockIdx.x * blockDim.x + threadIdx.x;
    int c = blockIdx.y;
    int n0 = 4 * p;
    float be0 = sigmoid_f(beta_raw[n0 & (H_DIM - 1)]);
    float be1 = sigmoid_f(beta_raw[(n0 + 1) & (H_DIM - 1)]);
    float be2 = sigmoid_f(beta_raw[(n0 + 2) & (H_DIM - 1)]);
    float be3 = sigmoid_f(beta_raw[(n0 + 3) & (H_DIM - 1)]);
    float4 mi = *(float4*)(g_inc + c * NB + n0);
    float m0 = mi.x, m1 = mi.y, m2 = mi.z, m3 = mi.w;
    const uint2* q = (const uint2*)(g_q16 + (size_t)c * LCH * NB) + p;
    uint2* a = (uint2*)(g_a16 + (size_t)c * LCH * NB) + p;
    #pragma unroll
    for (int i = 0; i < LCH; ++i) {
        uint2 u = q[(size_t)i * (NB / 4)];
        float2 v0 = __half22float2(*(__half2*)&u.x);
        float2 v1 = __half22float2(*(__half2*)&u.y);
        m0 = fmaf(be0, m0, v0.x);
        m1 = fmaf(be1, m1, v0.y);
        m2 = fmaf(be2, m2, v1.x);
        m3 = fmaf(be3, m3, v1.y);
        __half2 h0 = __floats2half2_rn(m0, m1);
        __half2 h1 = __floats2half2_rn(m2, m3);
        uint2 o; o.x = *(uint32_t*)&h0; o.y = *(uint32_t*)&h1;
        a[(size_t)i * (NB / 4)] = o;
    }
}

// ---------------- launch ----------------
extern "C" void kernel_launch(void* const* d_in, const int* in_sizes, int n_in,
                              void* d_out, int out_size) {
    (void)in_sizes; (void)n_in; (void)out_size;
    const float* x        = (const float*)d_in[0];
    const float* W_q      = (const float*)d_in[1];
    const float* b_q      = (const float*)d_in[2];
    const float* beta_raw = (const float*)d_in[3];
    const float* W_fc     = (const float*)d_in[4];
    const float* b_fc     = (const float*)d_in[5];
    float* out = (float*)d_out;

    cudaFuncSetAttribute(gemm_kernel, cudaFuncAttributeMaxDynamicSharedMemorySize, GEMM_SMEM);

    __half *wq16, *wf16, *a16, *q16;
    cudaGetSymbolAddress((void**)&wq16, g_wq16);
    cudaGetSymbolAddress((void**)&wf16, g_wf16);
    cudaGetSymbolAddress((void**)&a16,  g_a16);
    cudaGetSymbolAddress((void**)&q16,  g_q16);

    int n4x = M_TOTAL * K_TOTAL / 4;
    int n4w = H_DIM * H_DIM / 4;
    conv_fused<<<(n4x + 255) / 256, 256>>>(x, W_q, W_fc, n4x, n4w);

    gemm_kernel<<<GEMM_GRID, GTHREADS, GEMM_SMEM>>>(a16, wq16, b_q, q16, 0);

    dim3 sgrid(NB / 4 / 256, NCH);
    scan_pass1<<<sgrid, 256>>>(beta_raw);
    scan_pass2<<<NB / 256, 256>>>(beta_raw);
    scan_pass3<<<sgrid, 256>>>(beta_raw);

    gemm_kernel<<<GEMM_GRID, GTHREADS, GEMM_SMEM>>>(a16, wf16, b_fc, out, 1);
}

// round 14
// speedup vs baseline: 1.2861x; 1.0086x over previous
#include <cuda_runtime.h>
#include <cuda_fp16.h>
#include <cstdint>
#include <cstddef>

#define T_DIM 2048
#define B_DIM 8
#define H_DIM 1024
#define M_TOTAL (T_DIM * B_DIM)   // 16384
#define K_TOTAL H_DIM
#define N_TOTAL H_DIM
#define NB (B_DIM * H_DIM)        // 8192 scan chains
#define NCH 64
#define LCH 32

// ---------------- static scratch ----------------
__device__ __half g_a16[(size_t)M_TOTAL * K_TOTAL];  // x (fp16), later m (fp16)
__device__ __half g_q16[(size_t)M_TOTAL * K_TOTAL];  // q (fp16)
__device__ __half g_wq16[H_DIM * H_DIM];
__device__ __half g_wf16[H_DIM * H_DIM];
__device__ float  g_carry[NCH * NB];
__device__ float  g_inc[NCH * NB];

// ---------------- helpers ----------------
__device__ __forceinline__ uint32_t smem_u32(const void* p) {
    uint32_t a;
    asm("{ .reg .u64 t; cvta.to.shared.u64 t, %1; cvt.u32.u64 %0, t; }" : "=r"(a) : "l"(p));
    return a;
}
__device__ __forceinline__ uint32_t sw128(uint32_t x) { return x ^ ((x >> 3) & 0x70); }

__device__ __forceinline__ void cp16(uint32_t dst, const void* src) {
    unsigned long long g = (unsigned long long)__cvta_generic_to_global(src);
    asm volatile("cp.async.cg.shared.global [%0], [%1], 16;" :: "r"(dst), "l"(g));
}
__device__ __forceinline__ void ldsm4(uint32_t& r0, uint32_t& r1, uint32_t& r2, uint32_t& r3,
                                      uint32_t addr) {
    asm volatile("ldmatrix.sync.aligned.m8n8.x4.shared.b16 {%0,%1,%2,%3}, [%4];"
                 : "=r"(r0), "=r"(r1), "=r"(r2), "=r"(r3) : "r"(addr));
}
__device__ __forceinline__ void mma16816(float* c, const uint32_t* a, const uint32_t* b) {
    asm volatile(
        "mma.sync.aligned.m16n8k16.row.col.f32.f16.f16.f32 "
        "{%0,%1,%2,%3}, {%4,%5,%6,%7}, {%8,%9}, {%0,%1,%2,%3};"
        : "+f"(c[0]), "+f"(c[1]), "+f"(c[2]), "+f"(c[3])
        : "r"(a[0]), "r"(a[1]), "r"(a[2]), "r"(a[3]), "r"(b[0]), "r"(b[1]));
}

// ---------------- GEMM: C[m,n] = sum_k A[m,k]*W16[n,k] + bias[n] ----------------
#define TM 128
#define TN 128
#define KC 64
#define NCHUNK (K_TOTAL / KC)     // 16
#define NSTAGE 3
#define STG 32768                 // A 16KB + B 16KB
#define GEMM_SMEM (NSTAGE * STG)  // 98304
#define GTHREADS 128
#define NTILES ((M_TOTAL / TM) * (N_TOTAL / TN))   // 1024
#define GEMM_GRID 304             // 2 CTAs per SM, persistent

__device__ __forceinline__ void fill_stage(uint32_t s, int tid,
    const __half* __restrict__ A, const __half* __restrict__ B,
    int m_base, int n_base, int kb)
{
    #pragma unroll
    for (int i = 0; i < 8; ++i) {                 // A: 128 rows x 8 segs = 1024
        int seg = tid + i * 128;
        int row = seg >> 3, s8 = seg & 7;
        uint32_t sw = sw128((uint32_t)(row * 128 + s8 * 16));
        cp16(s + sw, A + (size_t)(m_base + row) * K_TOTAL + kb + s8 * 8);
    }
    #pragma unroll
    for (int i = 0; i < 8; ++i) {                 // B: 128 rows x 8 segs
        int seg = tid + i * 128;
        int row = seg >> 3, s8 = seg & 7;
        uint32_t sw = sw128((uint32_t)(row * 128 + s8 * 16));
        cp16(s + 16384 + sw, B + (size_t)(n_base + row) * K_TOTAL + kb + s8 * 8);
    }
    asm volatile("cp.async.commit_group;" ::: "memory");
}

// mode 0: store fp16, no relu.  mode 1: store fp32 with relu.
// Flat (tile, chunk) pipeline: stage cursor rolls continuously across tiles.
__global__ void __launch_bounds__(GTHREADS, 2) gemm_kernel(
    const __half* __restrict__ A, const __half* __restrict__ B,
    const float* __restrict__ bias, void* __restrict__ Cv, int mode)
{
    extern __shared__ char smem[];
    uint32_t sb = smem_u32(smem);
    int tid = threadIdx.x, lane = tid & 31, wid = tid >> 5;
    int wm = wid >> 1, wn = wid & 1;              // 2 x 2 warp grid, 64x64 warp tile

    int a_row = wm * 64 + (lane & 15);
    int a_kh  = (lane >> 4) * 16;
    int bsel  = lane >> 3;
    int b_joff = (bsel >> 1) * 8;
    int b_kh   = (bsel & 1) * 16;
    int b_row0 = wn * 64 + b_joff + (lane & 7);

    int ntile_cta = (NTILES - blockIdx.x + GEMM_GRID - 1) / GEMM_GRID;
    if (ntile_cta <= 0) return;
    int total = ntile_cta * NCHUNK;

    float acc[4][8][4];
    #pragma unroll
    for (int t = 0; t < 4; ++t)
        #pragma unroll
        for (int j = 0; j < 8; ++j)
            #pragma unroll
            for (int e = 0; e < 4; ++e) acc[t][j][e] = 0.f;

    {
        int t0 = blockIdx.x;
        int nb = (t0 & 7) * TN, mb = (t0 >> 3) * TM;
        fill_stage(sb + 0 * STG, tid, A, B, mb, nb, 0);
        if (total > 1) fill_stage(sb + 1 * STG, tid, A, B, mb, nb, KC);
    }

    uint32_t afr[2][4][4], bfr[2][8][2];

    for (int gc = 0; gc < total; ++gc) {
        if (gc < total - 1) asm volatile("cp.async.wait_group 1;" ::: "memory");
        else                asm volatile("cp.async.wait_group 0;" ::: "memory");
        __syncthreads();

        int gf = gc + 2;
        if (gf < total) {
            int tf = blockIdx.x + (gf >> 4) * GEMM_GRID;
            int nb = (tf & 7) * TN, mb = (tf >> 3) * TM;
            fill_stage(sb + (gf % NSTAGE) * STG, tid, A, B, mb, nb, (gf & 15) * KC);
        } else {
            asm volatile("cp.async.commit_group;" ::: "memory");
        }

        uint32_t sA = sb + (gc % NSTAGE) * STG;
        uint32_t sB = sA + 16384;

        #pragma unroll
        for (int t = 0; t < 4; ++t)
            ldsm4(afr[0][t][0], afr[0][t][1], afr[0][t][2], afr[0][t][3],
                  sA + sw128((uint32_t)((a_row + t * 16) * 128 + a_kh)));
        #pragma unroll
        for (int jp = 0; jp < 4; ++jp) {
            uint32_t r0, r1, r2, r3;
            ldsm4(r0, r1, r2, r3,
                  sB + sw128((uint32_t)((b_row0 + jp * 16) * 128 + b_kh)));
            bfr[0][jp * 2 + 0][0] = r0; bfr[0][jp * 2 + 0][1] = r1;
            bfr[0][jp * 2 + 1][0] = r2; bfr[0][jp * 2 + 1][1] = r3;
        }

        #pragma unroll
        for (int k16 = 0; k16 < 4; ++k16) {
            int cur = k16 & 1, nxt = cur ^ 1;
            if (k16 < 3) {
                int ko = (k16 + 1) * 32;
                #pragma unroll
                for (int t = 0; t < 4; ++t)
                    ldsm4(afr[nxt][t][0], afr[nxt][t][1], afr[nxt][t][2], afr[nxt][t][3],
                          sA + sw128((uint32_t)((a_row + t * 16) * 128 + ko + a_kh)));
                #pragma unroll
                for (int jp = 0; jp < 4; ++jp) {
                    uint32_t r0, r1, r2, r3;
                    ldsm4(r0, r1, r2, r3,
                          sB + sw128((uint32_t)((b_row0 + jp * 16) * 128 + ko + b_kh)));
                    bfr[nxt][jp * 2 + 0][0] = r0; bfr[nxt][jp * 2 + 0][1] = r1;
                    bfr[nxt][jp * 2 + 1][0] = r2; bfr[nxt][jp * 2 + 1][1] = r3;
                }
            }
            #pragma unroll
            for (int t = 0; t < 4; ++t)
                #pragma unroll
                for (int j = 0; j < 8; ++j)
                    mma16816(acc[t][j], afr[cur][t], bfr[cur][j]);
        }

        if ((gc & 15) == 15) {
            int tc = blockIdx.x + (gc >> 4) * GEMM_GRID;
            int n_base = (tc & 7) * TN, m_base = (tc >> 3) * TM;
            #pragma unroll
            for (int t = 0; t < 4; ++t) {
                int r0 = m_base + wm * 64 + t * 16 + (lane >> 2);
                #pragma unroll
                for (int j = 0; j < 8; ++j) {
                    int col = n_base + wn * 64 + j * 8 + (lane & 3) * 2;
                    float b0 = bias[col], b1 = bias[col + 1];
                    float v0 = acc[t][j][0] + b0;
                    float v1 = acc[t][j][1] + b1;
                    float v2 = acc[t][j][2] + b0;
                    float v3 = acc[t][j][3] + b1;
                    if (mode == 0) {
                        __half* Ch = (__half*)Cv;
                        *(__half2*)(Ch + (size_t)r0 * N_TOTAL + col) = __floats2half2_rn(v0, v1);
                        *(__half2*)(Ch + (size_t)(r0 + 8) * N_TOTAL + col) = __floats2half2_rn(v2, v3);
                    } else {
                        float* Cf = (float*)Cv;
                        v0 = fmaxf(v0, 0.f); v1 = fmaxf(v1, 0.f);
                        v2 = fmaxf(v2, 0.f); v3 = fmaxf(v3, 0.f);
                        *(float2*)(Cf + (size_t)r0 * N_TOTAL + col) = make_float2(v0, v1);
                        *(float2*)(Cf + (size_t)(r0 + 8) * N_TOTAL + col) = make_float2(v2, v3);
                    }
                    acc[t][j][0] = 0.f; acc[t][j][1] = 0.f;
                    acc[t][j][2] = 0.f; acc[t][j][3] = 0.f;
                }
            }
        }
    }
}

// ---------------- fused converts ----------------
__global__ void conv_fused(const float* __restrict__ x,
                           const float* __restrict__ wq, const float* __restrict__ wf,
                           int n4x, int n4w) {
    int i = blockIdx.x * blockDim.x + threadIdx.x;
    if (i < n4x) {
        float4 v = ((const float4*)x)[i];
        __half2 h0 = __floats2half2_rn(v.x, v.y);
        __half2 h1 = __floats2half2_rn(v.z, v.w);
        uint2 o; o.x = *(uint32_t*)&h0; o.y = *(uint32_t*)&h1;
        ((uint2*)g_a16)[i] = o;
    }
    if (i < n4w) {
        float4 a = ((const float4*)wq)[i];
        float4 b = ((const float4*)wf)[i];
        __half2 qa = __floats2half2_rn(a.x, a.y), qb = __floats2half2_rn(a.z, a.w);
        __half2 fa = __floats2half2_rn(b.x, b.y), fb = __floats2half2_rn(b.z, b.w);
        uint2 oq; oq.x = *(uint32_t*)&qa; oq.y = *(uint32_t*)&qb;
        uint2 of; of.x = *(uint32_t*)&fa; of.y = *(uint32_t*)&fb;
        ((uint2*)g_wq16)[i] = oq;
        ((uint2*)g_wf16)[i] = of;
    }
}

// ---------------- scan: m_t = beta*m_{t-1} + q_t (4 chains per thread) ----------------
__device__ __forceinline__ float sigmoid_f(float x) { return 1.f / (1.f + expf(-x)); }

__global__ void scan_pass1(const float* __restrict__ beta_raw) {
    int p = blockIdx.x * blockDim.x + threadIdx.x;   // quad index, 0..NB/4-1
    int c = blockIdx.y;
    int n0 = 4 * p;
    float be0 = sigmoid_f(beta_raw[n0 & (H_DIM - 1)]);
    float be1 = sigmoid_f(beta_raw[(n0 + 1) & (H_DIM - 1)]);
    float be2 = sigmoid_f(beta_raw[(n0 + 2) & (H_DIM - 1)]);
    float be3 = sigmoid_f(beta_raw[(n0 + 3) & (H_DIM - 1)]);
    const uint2* q = (const uint2*)(g_q16 + (size_t)c * LCH * NB) + p;
    float m0 = 0.f, m1 = 0.f, m2 = 0.f, m3 = 0.f;
    #pragma unroll
    for (int i = 0; i < LCH; ++i) {
        uint2 u = q[(size_t)i * (NB / 4)];
        float2 v0 = __half22float2(*(__half2*)&u.x);
        float2 v1 = __half22float2(*(__half2*)&u.y);
        m0 = fmaf(be0, m0, v0.x);
        m1 = fmaf(be1, m1, v0.y);
        m2 = fmaf(be2, m2, v1.x);
        m3 = fmaf(be3, m3, v1.y);
    }
    *(float4*)(g_carry + c * NB + n0) = make_float4(m0, m1, m2, m3);
}

// pass 2: all 64 carry loads issued up front (single latency exposure)
__global__ void scan_pass2(const float* __restrict__ beta_raw) {
    int n = blockIdx.x * blockDim.x + threadIdx.x;
    float beta = sigmoid_f(beta_raw[n & (H_DIM - 1)]);
    float b2 = beta * beta, b4 = b2 * b2, b8 = b4 * b4, b16 = b8 * b8;
    float bl = b16 * b16;  // beta^32 = beta^LCH
    float v[NCH];
    #pragma unroll
    for (int c = 0; c < NCH; ++c) v[c] = g_carry[c * NB + n];
    float P = 0.f;
    #pragma unroll
    for (int c = 0; c < NCH; ++c) {
        g_inc[c * NB + n] = P;
        P = fmaf(bl, P, v[c]);
    }
}

__global__ void scan_pass3(const float* __restrict__ beta_raw) {
    int p = blockIdx.x * blockDim.x + threadIdx.x;
    int c = blockIdx.y;
    int n0 = 4 * p;
    float be0 = sigmoid_f(beta_raw[n0 & (H_DIM - 1)]);
    float be1 = sigmoid_f(beta_raw[(n0 + 1) & (H_DIM - 1)]);
    float be2 = sigmoid_f(beta_raw[(n0 + 2) & (H_DIM - 1)]);
    float be3 = sigmoid_f(beta_raw[(n0 + 3) & (H_DIM - 1)]);
    float4 mi = *(float4*)(g_inc + c * NB + n0);
    float m0 = mi.x, m1 = mi.y, m2 = mi.z, m3 = mi.w;
    const uint2* q = (const uint2*)(g_q16 + (size_t)c * LCH * NB) + p;
    uint2* a = (uint2*)(g_a16 + (size_t)c * LCH * NB) + p;
    #pragma unroll
    for (int i = 0; i < LCH; ++i) {
        uint2 u = q[(size_t)i * (NB / 4)];
        float2 v0 = __half22float2(*(__half2*)&u.x);
        float2 v1 = __half22float2(*(__half2*)&u.y);
        m0 = fmaf(be0, m0, v0.x);
        m1 = fmaf(be1, m1, v0.y);
        m2 = fmaf(be2, m2, v1.x);
        m3 = fmaf(be3, m3, v1.y);
        __half2 h0 = __floats2half2_rn(m0, m1);
        __half2 h1 = __floats2half2_rn(m2, m3);
        uint2 o; o.x = *(uint32_t*)&h0; o.y = *(uint32_t*)&h1;
        a[(size_t)i * (NB / 4)] = o;
    }
}

// ---------------- launch ----------------
extern "C" void kernel_launch(void* const* d_in, const int* in_sizes, int n_in,
                              void* d_out, int out_size) {
    (void)in_sizes; (void)n_in; (void)out_size;
    const float* x        = (const float*)d_in[0];
    const float* W_q      = (const float*)d_in[1];
    const float* b_q      = (const float*)d_in[2];
    const float* beta_raw = (const float*)d_in[3];
    const float* W_fc     = (const float*)d_in[4];
    const float* b_fc     = (const float*)d_in[5];
    float* out = (float*)d_out;

    cudaFuncSetAttribute(gemm_kernel, cudaFuncAttributeMaxDynamicSharedMemorySize, GEMM_SMEM);

    __half *wq16, *wf16, *a16, *q16;
    cudaGetSymbolAddress((void**)&wq16, g_wq16);
    cudaGetSymbolAddress((void**)&wf16, g_wf16);
    cudaGetSymbolAddress((void**)&a16,  g_a16);
    cudaGetSymbolAddress((void**)&q16,  g_q16);

    int n4x = M_TOTAL * K_TOTAL / 4;
    int n4w = H_DIM * H_DIM / 4;
    conv_fused<<<(n4x + 255) / 256, 256>>>(x, W_q, W_fc, n4x, n4w);

    gemm_kernel<<<GEMM_GRID, GTHREADS, GEMM_SMEM>>>(a16, wq16, b_q, q16, 0);

    dim3 sgrid(NB / 4 / 256, NCH);
    scan_pass1<<<sgrid, 256>>>(beta_raw);
    scan_pass2<<<NB / 256, 256>>>(beta_raw);
    scan_pass3<<<sgrid, 256>>>(beta_raw);

    gemm_kernel<<<GEMM_GRID, GTHREADS, GEMM_SMEM>>>(a16, wf16, b_fc, out, 1);
}